// round 14
// baseline (speedup 1.0000x reference)
#include <cuda_runtime.h>
#include <cuda_fp16.h>
#include <math.h>
#include <cstdint>

#define NN 5000
#define BB 8
#define TT 40000      // BB*NN
#define EE 40000
#define SS 12
#define FF 16
#define HH 128
#define LL 2
#define NE (EE + NN)  // CSR entries (edges + self loops)

// ---------------- device scratch (static: no allocation allowed) ------------
__device__ float g_deg[NN];
__device__ float g_dis[NN];
__device__ int   g_cnt[NN];
__device__ int   g_ptr[NN + 1];
__device__ int   g_wpos[NN];
__device__ int   g_src[NE];
__device__ float g_wv[NE];
__device__ int   g_key[NE];
__device__ uint2 g_ew[NE];   // packed: .x = src*32 (uint2 elems), .y = w bits

__device__ __half g_Xt[(size_t)SS * TT * HH];     // relu(lin_in), all steps, fp16
__device__ float  g_h[(size_t)LL * TT * HH];      // hidden states fp32 (master)
__device__ __half g_hf[(size_t)LL * TT * HH];     // fp16 copy of h (gather source)
__device__ __half g_AX[(size_t)TT * HH];          // Ax half (for fused_c), fp16
__device__ __half g_RH[(size_t)TT * HH];          // r * h fp16 (gather source)
__device__ float  g_U[(size_t)TT * HH];           // u gate fp32
__device__ __half g_WruT[(size_t)LL * 256 * 256]; // [n][k] fp16: n<128 W_r, n>=128 W_u
__device__ __half g_WcT[(size_t)LL * 128 * 256];  // [n][k] fp16
__device__ float  g_psum[160 * HH];
__device__ float  g_psq[160 * HH];
__device__ float  g_mean[HH];
__device__ float  g_rstd[HH];

// ---------------- asm helpers -------------------------------------------------
__device__ __forceinline__ uint32_t smem_u32(const void* p) {
    uint32_t a;
    asm("{ .reg .u64 t; cvta.to.shared.u64 t, %1; cvt.u32.u64 %0, t; }"
        : "=r"(a) : "l"(p));
    return a;
}
#define CP_ASYNC16(dst, src) \
    asm volatile("cp.async.cg.shared.global [%0], [%1], 16;" :: "r"(dst), "l"(src))
#define CP_COMMIT() asm volatile("cp.async.commit_group;" ::: "memory")
#define CP_WAIT1()  asm volatile("cp.async.wait_group 1;" ::: "memory")
#define CP_WAIT0()  asm volatile("cp.async.wait_group 0;" ::: "memory")

__device__ __forceinline__ void ldsm_x4(uint32_t& r0, uint32_t& r1,
                                        uint32_t& r2, uint32_t& r3, uint32_t addr) {
    asm volatile("ldmatrix.sync.aligned.m8n8.x4.shared.b16 {%0,%1,%2,%3}, [%4];"
        : "=r"(r0), "=r"(r1), "=r"(r2), "=r"(r3) : "r"(addr));
}

__device__ __forceinline__ void mma_f16(float* c, const uint32_t* a, const uint32_t* b) {
    asm volatile(
        "mma.sync.aligned.m16n8k16.row.col.f32.f16.f16.f32 "
        "{%0,%1,%2,%3}, {%4,%5,%6,%7}, {%8,%9}, {%0,%1,%2,%3};"
        : "+f"(c[0]), "+f"(c[1]), "+f"(c[2]), "+f"(c[3])
        : "r"(a[0]), "r"(a[1]), "r"(a[2]), "r"(a[3]), "r"(b[0]), "r"(b[1]));
}

// ---------------- single-block cooperative graph prep -----------------------
__global__ void prep_all(const int* __restrict__ ei, const float* __restrict__ ew) {
    int tid = threadIdx.x;                       // 1024 threads, 1 block
    for (int i = tid; i < NN; i += 1024) { g_deg[i] = 1.0f; g_cnt[i] = 1; }
    __syncthreads();
    for (int e = tid; e < EE; e += 1024) {
        int c = ei[EE + e];
        atomicAdd(&g_deg[c], ew[e]);
        atomicAdd(&g_cnt[c], 1);
    }
    __syncthreads();
    for (int i = tid; i < NN; i += 1024) g_dis[i] = rsqrtf(g_deg[i]);
    __syncthreads();
    __shared__ int sh[1024];
    __shared__ int carry;
    if (tid == 0) carry = 0;
    __syncthreads();
    for (int base = 0; base < NN; base += 1024) {
        int i = base + tid;
        int v = (i < NN) ? g_cnt[i] : 0;
        sh[tid] = v;
        __syncthreads();
        for (int off = 1; off < 1024; off <<= 1) {
            int t = (tid >= off) ? sh[tid - off] : 0;
            __syncthreads();
            sh[tid] += t;
            __syncthreads();
        }
        int excl = sh[tid] - v + carry;
        if (i < NN) g_ptr[i] = excl;
        __syncthreads();
        if (tid == 1023) carry += sh[1023];
        __syncthreads();
    }
    if (tid == 0) g_ptr[NN] = carry;
    __syncthreads();
    for (int i = tid; i < NN; i += 1024) {
        int p = g_ptr[i];
        g_src[p] = i;
        g_wv[p]  = g_dis[i] * g_dis[i];
        g_key[p] = -1;
        g_wpos[i] = p + 1;
    }
    __syncthreads();
    for (int e = tid; e < EE; e += 1024) {
        int r = ei[e];
        int c = ei[EE + e];
        int p = atomicAdd(&g_wpos[c], 1);
        g_src[p] = r;
        g_wv[p]  = g_dis[r] * ew[e] * g_dis[c];
        g_key[p] = e;
    }
    __syncthreads();
    for (int c = tid; c < NN; c += 1024) {
        int s0 = g_ptr[c] + 1, s1 = g_ptr[c + 1];
        for (int i = s0 + 1; i < s1; i++) {
            int k = g_key[i]; int sr = g_src[i]; float w = g_wv[i];
            int j = i - 1;
            while (j >= s0 && g_key[j] > k) {
                g_key[j + 1] = g_key[j]; g_src[j + 1] = g_src[j]; g_wv[j + 1] = g_wv[j];
                j--;
            }
            g_key[j + 1] = k; g_src[j + 1] = sr; g_wv[j + 1] = w;
        }
    }
    __syncthreads();
    for (int i = tid; i < NE; i += 1024) {
        uint2 m;
        m.x = (uint32_t)g_src[i] * 32u;
        m.y = __float_as_uint(g_wv[i]);
        g_ew[i] = m;
    }
}

// ---------------- weight pack (fp16) + zero h (fp32 + fp16) ------------------
#define W1 (LL * 256 * 256)
#define W2 (LL * 128 * 256)
#define W3 (LL * TT * HH)
#define MISC_BLOCKS ((W1 + W2 + 2 * W3 + 127) / 128)

__global__ void init_misc(const float* __restrict__ convW) {
    size_t i = (size_t)blockIdx.x * 128 + threadIdx.x;
    if (i < W1) {
        int l = (int)(i >> 16), rem = (int)(i & 65535);
        int n = rem >> 8, k = rem & 255;
        int g = n >> 7, j = n & 127;
        g_WruT[i] = __float2half(convW[((size_t)(l * 3 + g) * 256 + k) * 128 + j]);
    } else if (i < (size_t)W1 + W2) {
        size_t q = i - W1;
        int l = (int)(q >> 15), rem = (int)(q & 32767);
        int n = rem >> 8, k = rem & 255;
        g_WcT[q] = __float2half(convW[((size_t)(l * 3 + 2) * 256 + k) * 128 + n]);
    } else if (i < (size_t)W1 + W2 + W3) {
        g_h[i - W1 - W2] = 0.0f;
    } else if (i < (size_t)W1 + W2 + 2 * W3) {
        g_hf[i - W1 - W2 - W3] = __float2half(0.0f);
    }
}

// ---------------- lin_in, tiled: 64 nodes / 256-thread block -----------------
__global__ void __launch_bounds__(256) linin_tiled(const float* __restrict__ x_seq,
                                                   const float* __restrict__ W,
                                                   const float* __restrict__ bias) {
    __shared__ float sW[FF * HH];
    __shared__ float sx[64 * FF];
    __shared__ float sb[HH];
    int tid = threadIdx.x;
    size_t base = (size_t)blockIdx.x * 64;
    int s = (int)(base / TT);
    int t_base = (int)(base - (size_t)s * TT);

    for (int i = tid; i < FF * HH; i += 256) sW[i] = W[i];
    if (tid < HH) sb[tid] = bias[tid];
    {
        int node = tid >> 2, fg = (tid & 3) * 4;
        int t = t_base + node;
        int b = t / NN, n = t - b * NN;
        float4 v = *reinterpret_cast<const float4*>(
            &x_seq[(((size_t)b * SS + s) * NN + n) * FF + fg]);
        *reinterpret_cast<float4*>(&sx[node * FF + fg]) = v;
    }
    __syncthreads();

    int j = tid & 127, nh = tid >> 7;
    __half* outp = g_Xt + (size_t)s * TT * HH + (size_t)t_base * HH;
#pragma unroll 4
    for (int nd = nh * 32; nd < nh * 32 + 32; nd++) {
        float acc = sb[j];
#pragma unroll
        for (int k = 0; k < FF; k++) acc = fmaf(sx[nd * FF + k], sW[k * HH + j], acc);
        outp[(size_t)nd * HH + j] = __float2half(fmaxf(acc, 0.0f));
    }
}

// ---------------- shared gather helper (4 cols per thread) -------------------
__device__ __forceinline__ void gather4(const uint2* p, int s0, int s1,
                                        float& a0, float& a1, float& a2, float& a3) {
    a0 = a1 = a2 = a3 = 0.f;
    int e = s0;
    for (; e + 4 <= s1; e += 4) {
        uint2 m0 = g_ew[e],     m1 = g_ew[e + 1];
        uint2 m2 = g_ew[e + 2], m3 = g_ew[e + 3];
        float w0 = __uint_as_float(m0.y), w1 = __uint_as_float(m1.y);
        float w2 = __uint_as_float(m2.y), w3 = __uint_as_float(m3.y);
        uint2 v0 = __ldg(p + m0.x), v1 = __ldg(p + m1.x);
        uint2 v2 = __ldg(p + m2.x), v3 = __ldg(p + m3.x);
        float2 p00 = __half22float2(*reinterpret_cast<__half2*>(&v0.x));
        float2 p01 = __half22float2(*reinterpret_cast<__half2*>(&v0.y));
        float2 p10 = __half22float2(*reinterpret_cast<__half2*>(&v1.x));
        float2 p11 = __half22float2(*reinterpret_cast<__half2*>(&v1.y));
        float2 p20 = __half22float2(*reinterpret_cast<__half2*>(&v2.x));
        float2 p21 = __half22float2(*reinterpret_cast<__half2*>(&v2.y));
        float2 p30 = __half22float2(*reinterpret_cast<__half2*>(&v3.x));
        float2 p31 = __half22float2(*reinterpret_cast<__half2*>(&v3.y));
        a0 = fmaf(w0, p00.x, a0); a1 = fmaf(w0, p00.y, a1);
        a2 = fmaf(w0, p01.x, a2); a3 = fmaf(w0, p01.y, a3);
        a0 = fmaf(w1, p10.x, a0); a1 = fmaf(w1, p10.y, a1);
        a2 = fmaf(w1, p11.x, a2); a3 = fmaf(w1, p11.y, a3);
        a0 = fmaf(w2, p20.x, a0); a1 = fmaf(w2, p20.y, a1);
        a2 = fmaf(w2, p21.x, a2); a3 = fmaf(w2, p21.y, a3);
        a0 = fmaf(w3, p30.x, a0); a1 = fmaf(w3, p30.y, a1);
        a2 = fmaf(w3, p31.x, a2); a3 = fmaf(w3, p31.y, a3);
    }
    for (; e < s1; e++) {
        uint2 m = g_ew[e];
        float w = __uint_as_float(m.y);
        uint2 v = __ldg(p + m.x);
        float2 q0 = __half22float2(*reinterpret_cast<__half2*>(&v.x));
        float2 q1 = __half22float2(*reinterpret_cast<__half2*>(&v.y));
        a0 = fmaf(w, q0.x, a0); a1 = fmaf(w, q0.y, a1);
        a2 = fmaf(w, q1.x, a2); a3 = fmaf(w, q1.y, a3);
    }
}

// ---------------- fused kernels: SpMM + fp16 MMA GEMM, M=64 tiles ------------
#define LDM2 20                          // u32 per row per chunk (16 data + 4 pad)
#define A64STG_U32 (64 * LDM2)           // A chunk: 1280 u32 = 5120 B
#define A64STG_B   (A64STG_U32 * 4)
#define B64STG_U32 (128 * LDM2)          // B stage: 2560 u32 = 10240 B
#define B64STG_B   (B64STG_U32 * 4)
#define AFULL_U32  (8 * A64STG_U32)      // full A tile: 8 chunks
#define GSMEMF ((AFULL_U32 + 3 * B64STG_U32) * 4)   // 71680 B

// ---- K1: gather [Ax|Ah] into smem + both r,u gate GEMMs ---------------------
__global__ void __launch_bounds__(256, 3) fused_ru(int l, int s,
                                                   const float* __restrict__ convB) {
    extern __shared__ uint32_t smem[];
    uint32_t* Afull = smem;                 // [8][A64STG_U32]
    uint32_t* Bs    = smem + AFULL_U32;     // [3][B64STG_U32]

    int tid = threadIdx.x;
    int wid = tid >> 5, lane = tid & 31;
    int m0 = blockIdx.x * 64;

    const __half* WT0 = g_WruT + (size_t)l * 256 * 256;

    // B copy slots (2 x 16B per thread per chunk)
    uint32_t bdst[2];
    int brow[2], bq[2];
#pragma unroll
    for (int it = 0; it < 2; it++) {
        int idx = tid + it * 256;
        brow[it] = idx >> 2; bq[it] = idx & 3;
        bdst[it] = smem_u32(Bs) + (uint32_t)(brow[it] * LDM2 + bq[it] * 4) * 4u;
    }

    // y=0 B prologue (chunks 0,1) — overlaps with gather
#pragma unroll
    for (int pc = 0; pc < 2; pc++) {
#pragma unroll
        for (int it = 0; it < 2; it++)
            CP_ASYNC16(bdst[it] + pc * B64STG_B,
                       WT0 + (size_t)brow[it] * 256 + pc * 32 + bq[it] * 8);
        CP_COMMIT();
    }

    // ---- Phase A: gather 64 nodes x [Ax|Ah] into Afull (+ Ax to gmem) ----
    {
        int node_in = tid >> 6;            // 0..3
        int sub = (tid >> 5) & 1;          // 0 = x, 1 = h
        int glane = tid & 31;
        const __half* xsrc = (l == 0) ? (g_Xt + (size_t)s * TT * HH) : g_hf;
        const __half* S = sub ? (g_hf + (size_t)l * TT * HH) : xsrc;
        int g = sub * 128 + glane * 4;
        int chunk = g >> 5, cslot = (g & 31) >> 1;
        uint32_t* sdst = Afull + chunk * A64STG_U32 + cslot;
        for (int pass = 0; pass < 16; pass++) {
            int t = m0 + pass * 4 + node_in;
            int c = t % NN;
            int base = t - c;
            const uint2* p = reinterpret_cast<const uint2*>(S) + base * 32 + glane;
            float a0, a1, a2, a3;
            gather4(p, g_ptr[c], g_ptr[c + 1], a0, a1, a2, a3);
            __half2 h0 = __floats2half2_rn(a0, a1);
            __half2 h1 = __floats2half2_rn(a2, a3);
            int row = pass * 4 + node_in;
            uint32_t* d = sdst + row * LDM2;
            d[0] = *reinterpret_cast<uint32_t*>(&h0);
            d[1] = *reinterpret_cast<uint32_t*>(&h1);
            if (sub == 0) {
                uint2 o;
                o.x = *reinterpret_cast<uint32_t*>(&h0);
                o.y = *reinterpret_cast<uint32_t*>(&h1);
                *(reinterpret_cast<uint2*>(g_AX + (size_t)t * HH) + glane) = o;
            }
        }
    }

    // ---- Phase B: two gate mainloops from resident A ----
    int row_in = lane >> 2, kq = lane & 3;
    int wm = wid & 1, wn = wid >> 1;       // 2x4 warp grid, warp tile 32x32
    uint32_t aoff[2], boff[2];
#pragma unroll
    for (int i = 0; i < 2; i++)
        aoff[i] = (uint32_t)((wm * 32 + i * 16 + (lane & 15)) * LDM2 + (lane >> 4) * 4) * 4u;
#pragma unroll
    for (int jp = 0; jp < 2; jp++)
        boff[jp] = (uint32_t)((wn * 32 + jp * 16 + (lane & 15)) * LDM2 + (lane >> 4) * 4) * 4u;
    uint32_t abase0 = smem_u32(Afull), bbase0 = smem_u32(Bs);

    const float* Hst = g_h + (size_t)l * TT * HH;

    for (int y = 0; y < 2; y++) {
        const __half* WT  = WT0 + (size_t)y * 128 * 256;
        const float* bias = convB + (size_t)l * 3 * HH + (size_t)y * HH;
        if (y == 1) {
            __syncthreads();               // stages free after y=0 compute
#pragma unroll
            for (int pc = 0; pc < 2; pc++) {
#pragma unroll
                for (int it = 0; it < 2; it++)
                    CP_ASYNC16(bdst[it] + pc * B64STG_B,
                               WT + (size_t)brow[it] * 256 + pc * 32 + bq[it] * 8);
                CP_COMMIT();
            }
        }

        float acc[2][4][4];
#pragma unroll
        for (int i = 0; i < 2; i++)
#pragma unroll
            for (int j = 0; j < 4; j++)
#pragma unroll
                for (int q = 0; q < 4; q++) acc[i][j][q] = 0.0f;

#pragma unroll
        for (int kc = 0; kc < 8; kc++) {
            if (kc < 7) CP_WAIT1();
            else CP_WAIT0();
            __syncthreads();
            if (kc + 2 < 8) {
                int nst = (kc + 2) % 3;
#pragma unroll
                for (int it = 0; it < 2; it++)
                    CP_ASYNC16(bdst[it] + nst * B64STG_B,
                               WT + (size_t)brow[it] * 256 + (kc + 2) * 32 + bq[it] * 8);
                CP_COMMIT();
            }
            uint32_t abase = abase0 + kc * A64STG_B;
            uint32_t bbase = bbase0 + (kc % 3) * B64STG_B;
#pragma unroll
            for (int ks = 0; ks < 2; ks++) {
                uint32_t a[2][4], b[4][2];
#pragma unroll
                for (int i = 0; i < 2; i++)
                    ldsm_x4(a[i][0], a[i][1], a[i][2], a[i][3], abase + aoff[i] + ks * 32);
#pragma unroll
                for (int jp = 0; jp < 2; jp++)
                    ldsm_x4(b[2 * jp][0], b[2 * jp + 1][0], b[2 * jp][1], b[2 * jp + 1][1],
                            bbase + boff[jp] + ks * 32);
#pragma unroll
                for (int i = 0; i < 2; i++)
#pragma unroll
                    for (int j = 0; j < 4; j++)
                        mma_f16(acc[i][j], a[i], b[j]);
            }
        }

        // epilogue
#pragma unroll
        for (int i = 0; i < 2; i++) {
            int r0 = m0 + wm * 32 + i * 16 + row_in;
#pragma unroll
            for (int half = 0; half < 2; half++) {
                int m = r0 + half * 8;
#pragma unroll
                for (int j = 0; j < 4; j++) {
                    int n = wn * 32 + j * 8 + 2 * kq;
                    float v0 = acc[i][j][half * 2 + 0] + bias[n];
                    float v1 = acc[i][j][half * 2 + 1] + bias[n + 1];
                    float s0 = 1.0f / (1.0f + expf(-v0));
                    float s1 = 1.0f / (1.0f + expf(-v1));
                    size_t o = (size_t)m * HH + n;
                    if (y == 0) {
                        float2 hv = *reinterpret_cast<const float2*>(&Hst[o]);
                        __half2 rv = __floats2half2_rn(s0 * hv.x, s1 * hv.y);
                        *reinterpret_cast<__half2*>(&g_RH[o]) = rv;
                    } else {
                        float2 uv; uv.x = s0; uv.y = s1;
                        *reinterpret_cast<float2*>(&g_U[o]) = uv;
                    }
                }
            }
        }
    }
}

// ---- K3: load Ax + gather Arh into smem + candidate GEMM --------------------
__global__ void __launch_bounds__(256, 3) fused_c(int l, const float* __restrict__ convB) {
    extern __shared__ uint32_t smem[];
    uint32_t* Afull = smem;                 // [8][A64STG_U32]
    uint32_t* Bs    = smem + AFULL_U32;     // [3][B64STG_U32]

    int tid = threadIdx.x;
    int wid = tid >> 5, lane = tid & 31;
    int m0 = blockIdx.x * 64;

    const __half* WT  = g_WcT + (size_t)l * 128 * 256;
    const float* bias = convB + (size_t)(l * 3 + 2) * HH;

    uint32_t bdst[2];
    int brow[2], bq[2];
#pragma unroll
    for (int it = 0; it < 2; it++) {
        int idx = tid + it * 256;
        brow[it] = idx >> 2; bq[it] = idx & 3;
        bdst[it] = smem_u32(Bs) + (uint32_t)(brow[it] * LDM2 + bq[it] * 4) * 4u;
    }

    // Ax load (chunks 0..3) : 4 x 16B per thread, one group
#pragma unroll
    for (int it = 0; it < 4; it++) {
        int idx = tid + it * 256;            // 0..1023
        int row = idx >> 4, slot = idx & 15;
        int chunk = slot >> 2, q = slot & 3;
        CP_ASYNC16(smem_u32(Afull) + (uint32_t)(chunk * A64STG_U32 + row * LDM2 + q * 4) * 4u,
                   g_AX + (size_t)(m0 + row) * HH + chunk * 32 + q * 8);
    }
    CP_COMMIT();
    // B prologue (chunks 0,1)
#pragma unroll
    for (int pc = 0; pc < 2; pc++) {
#pragma unroll
        for (int it = 0; it < 2; it++)
            CP_ASYNC16(bdst[it] + pc * B64STG_B,
                       WT + (size_t)brow[it] * 256 + pc * 32 + bq[it] * 8);
        CP_COMMIT();
    }

    // gather Arh into chunks 4..7
    {
        int node_in = tid >> 5;              // 0..7
        int glane = tid & 31;
        int g = 128 + glane * 4;
        int chunk = g >> 5, cslot = (g & 31) >> 1;
        uint32_t* sdst = Afull + chunk * A64STG_U32 + cslot;
        for (int pass = 0; pass < 8; pass++) {
            int t = m0 + pass * 8 + node_in;
            int c = t % NN;
            int base = t - c;
            const uint2* p = reinterpret_cast<const uint2*>(g_RH) + base * 32 + glane;
            float a0, a1, a2, a3;
            gather4(p, g_ptr[c], g_ptr[c + 1], a0, a1, a2, a3);
            __half2 h0 = __floats2half2_rn(a0, a1);
            __half2 h1 = __floats2half2_rn(a2, a3);
            int row = pass * 8 + node_in;
            uint32_t* d = sdst + row * LDM2;
            d[0] = *reinterpret_cast<uint32_t*>(&h0);
            d[1] = *reinterpret_cast<uint32_t*>(&h1);
        }
    }

    int row_in = lane >> 2, kq = lane & 3;
    int wm = wid & 1, wn = wid >> 1;
    uint32_t aoff[2], boff[2];
#pragma unroll
    for (int i = 0; i < 2; i++)
        aoff[i] = (uint32_t)((wm * 32 + i * 16 + (lane & 15)) * LDM2 + (lane >> 4) * 4) * 4u;
#pragma unroll
    for (int jp = 0; jp < 2; jp++)
        boff[jp] = (uint32_t)((wn * 32 + jp * 16 + (lane & 15)) * LDM2 + (lane >> 4) * 4) * 4u;
    uint32_t abase0 = smem_u32(Afull), bbase0 = smem_u32(Bs);

    float acc[2][4][4];
#pragma unroll
    for (int i = 0; i < 2; i++)
#pragma unroll
        for (int j = 0; j < 4; j++)
#pragma unroll
            for (int q = 0; q < 4; q++) acc[i][j][q] = 0.0f;

#pragma unroll
    for (int kc = 0; kc < 8; kc++) {
        if (kc < 7) CP_WAIT1();
        else CP_WAIT0();
        __syncthreads();
        if (kc + 2 < 8) {
            int nst = (kc + 2) % 3;
#pragma unroll
            for (int it = 0; it < 2; it++)
                CP_ASYNC16(bdst[it] + nst * B64STG_B,
                           WT + (size_t)brow[it] * 256 + (kc + 2) * 32 + bq[it] * 8);
            CP_COMMIT();
        }
        uint32_t abase = abase0 + kc * A64STG_B;
        uint32_t bbase = bbase0 + (kc % 3) * B64STG_B;
#pragma unroll
        for (int ks = 0; ks < 2; ks++) {
            uint32_t a[2][4], b[4][2];
#pragma unroll
            for (int i = 0; i < 2; i++)
                ldsm_x4(a[i][0], a[i][1], a[i][2], a[i][3], abase + aoff[i] + ks * 32);
#pragma unroll
            for (int jp = 0; jp < 2; jp++)
                ldsm_x4(b[2 * jp][0], b[2 * jp + 1][0], b[2 * jp][1], b[2 * jp + 1][1],
                        bbase + boff[jp] + ks * 32);
#pragma unroll
            for (int i = 0; i < 2; i++)
#pragma unroll
                for (int j = 0; j < 4; j++)
                    mma_f16(acc[i][j], a[i], b[j]);
        }
    }

    float* Hst = g_h + (size_t)l * TT * HH;
    __half* Hf = g_hf + (size_t)l * TT * HH;
#pragma unroll
    for (int i = 0; i < 2; i++) {
        int r0 = m0 + wm * 32 + i * 16 + row_in;
#pragma unroll
        for (int half = 0; half < 2; half++) {
            int m = r0 + half * 8;
#pragma unroll
            for (int j = 0; j < 4; j++) {
                int n = wn * 32 + j * 8 + 2 * kq;
                float v0 = acc[i][j][half * 2 + 0] + bias[n];
                float v1 = acc[i][j][half * 2 + 1] + bias[n + 1];
                float c0 = tanhf(v0), c1 = tanhf(v1);
                size_t o = (size_t)m * HH + n;
                float2 uv = *reinterpret_cast<const float2*>(&g_U[o]);
                float2 hv = *reinterpret_cast<const float2*>(&Hst[o]);
                hv.x = uv.x * hv.x + (1.0f - uv.x) * c0;
                hv.y = uv.y * hv.y + (1.0f - uv.y) * c1;
                *reinterpret_cast<float2*>(&Hst[o]) = hv;
                *reinterpret_cast<__half2*>(&Hf[o]) = __floats2half2_rn(hv.x, hv.y);
            }
        }
    }
}

// ---------------- batchnorm + output -----------------------------------------
__global__ void bn_partial() {
    int j = threadIdx.x;
    int b = blockIdx.x;
    const float* h1 = g_h + (size_t)(LL - 1) * TT * HH;
    float s = 0.0f, q = 0.0f;
    int r0 = b * (TT / 160), r1 = r0 + (TT / 160);
    for (int r = r0; r < r1; r++) {
        float v = h1[(size_t)r * HH + j];
        s += v; q += v * v;
    }
    g_psum[b * HH + j] = s;
    g_psq[b * HH + j]  = q;
}

__global__ void bn_final() {
    int j = threadIdx.x;
    float s = 0.0f, q = 0.0f;
    for (int b = 0; b < 160; b++) { s += g_psum[b * HH + j]; q += g_psq[b * HH + j]; }
    float m = s / (float)TT;
    float var = q / (float)TT - m * m;
    g_mean[j] = m;
    g_rstd[j] = rsqrtf(var + 1e-5f);
}

__global__ void final_kernel(const float* __restrict__ Wout,
                             const float* __restrict__ bout,
                             const float* __restrict__ gamma,
                             const float* __restrict__ beta,
                             float* __restrict__ out) {
    int warp = (blockIdx.x * blockDim.x + threadIdx.x) >> 5;
    int lane = threadIdx.x & 31;
    if (warp >= TT) return;
    const float* h1 = g_h + (size_t)(LL - 1) * TT * HH + (size_t)warp * HH;
    float a0 = 0.f, a1 = 0.f, a2 = 0.f, a3 = 0.f;
    for (int k = lane; k < HH; k += 32) {
        float v = (h1[k] - g_mean[k]) * g_rstd[k] * gamma[k] + beta[k];
        v = fmaxf(v, 0.0f);
        a0 = fmaf(v, Wout[k * 4 + 0], a0);
        a1 = fmaf(v, Wout[k * 4 + 1], a1);
        a2 = fmaf(v, Wout[k * 4 + 2], a2);
        a3 = fmaf(v, Wout[k * 4 + 3], a3);
    }
#pragma unroll
    for (int o = 16; o; o >>= 1) {
        a0 += __shfl_xor_sync(0xFFFFFFFFu, a0, o);
        a1 += __shfl_xor_sync(0xFFFFFFFFu, a1, o);
        a2 += __shfl_xor_sync(0xFFFFFFFFu, a2, o);
        a3 += __shfl_xor_sync(0xFFFFFFFFu, a3, o);
    }
    if (lane == 0) {
        a0 += bout[0]; a1 += bout[1]; a2 += bout[2]; a3 += bout[3];
        float mx = fmaxf(fmaxf(a0, a1), fmaxf(a2, a3));
        float se = expf(a0 - mx) + expf(a1 - mx) + expf(a2 - mx) + expf(a3 - mx);
        float lse = mx + logf(se);
        out[(size_t)warp * 4 + 0] = a0 - lse;
        out[(size_t)warp * 4 + 1] = a1 - lse;
        out[(size_t)warp * 4 + 2] = a2 - lse;
        out[(size_t)warp * 4 + 3] = a3 - lse;
    }
}

// ---------------- host orchestration -----------------------------------------
extern "C" void kernel_launch(void* const* d_in, const int* in_sizes, int n_in,
                              void* d_out, int out_size) {
    const float* x_seq      = (const float*)d_in[0];
    const int*   edge_index = (const int*)  d_in[1];
    const float* edge_weight= (const float*)d_in[2];
    const float* lin_in_W   = (const float*)d_in[3];
    const float* lin_in_b   = (const float*)d_in[4];
    const float* convW      = (const float*)d_in[5];
    const float* convB      = (const float*)d_in[6];
    const float* bn_gamma   = (const float*)d_in[7];
    const float* bn_beta    = (const float*)d_in[8];
    const float* lin_out_W  = (const float*)d_in[9];
    const float* lin_out_b  = (const float*)d_in[10];
    float* out = (float*)d_out;
    (void)in_sizes; (void)n_in; (void)out_size;

    cudaFuncSetAttribute(fused_ru, cudaFuncAttributeMaxDynamicSharedMemorySize, GSMEMF);
    cudaFuncSetAttribute(fused_c,  cudaFuncAttributeMaxDynamicSharedMemorySize, GSMEMF);

    // launches: 1 prep, 2 init_misc, 3 linin, 4 fused_ru (ncu slot)
    prep_all<<<1, 1024>>>(edge_index, edge_weight);
    init_misc<<<MISC_BLOCKS, 128>>>(convW);
    linin_tiled<<<SS * TT / 64, 256>>>(x_seq, lin_in_W, lin_in_b);

    int grid = TT / 64;   // 625

    for (int s = 0; s < SS; s++) {
        for (int l = 0; l < LL; l++) {
            fused_ru<<<grid, 256, GSMEMF>>>(l, s, convB);
            fused_c <<<grid, 256, GSMEMF>>>(l, convB);
        }
    }

    bn_partial<<<160, 128>>>();
    bn_final<<<1, 128>>>();
    final_kernel<<<(TT * 32 + 255) / 256, 256>>>(lin_out_W, lin_out_b,
                                                 bn_gamma, bn_beta, out);
}

// round 15
// speedup vs baseline: 1.3426x; 1.3426x over previous
#include <cuda_runtime.h>
#include <cuda_fp16.h>
#include <math.h>
#include <cstdint>

#define NN 5000
#define BB 8
#define TT 40000      // BB*NN
#define EE 40000
#define SS 12
#define FF 16
#define HH 128
#define LL 2
#define NE (EE + NN)  // CSR entries (edges + self loops)

// ---------------- device scratch (static: no allocation allowed) ------------
__device__ float g_deg[NN];
__device__ float g_dis[NN];
__device__ int   g_cnt[NN];
__device__ int   g_ptr[NN + 1];
__device__ int   g_wpos[NN];
__device__ int   g_src[NE];
__device__ float g_wv[NE];
__device__ int   g_key[NE];
__device__ uint2 g_ew[NE];   // packed: .x = src*32 (uint2 elems), .y = w bits

__device__ __half g_Xt[(size_t)SS * TT * HH];     // relu(lin_in), all steps, fp16
__device__ float  g_h[(size_t)LL * TT * HH];      // hidden states fp32 (master)
__device__ __half g_hf[(size_t)LL * TT * HH];     // fp16 copy of h (gather source)
__device__ __half g_AXH[(size_t)TT * 2 * HH];     // [Ax | Ah] / [Ax | Arh] fp16
__device__ __half g_RH[(size_t)TT * HH];          // r * h fp16 (gather source)
__device__ __half g_U[(size_t)TT * HH];           // u gate fp16
__device__ __half g_WruT[(size_t)LL * 256 * 256]; // [n][k] fp16: n<128 W_r, n>=128 W_u
__device__ __half g_WcT[(size_t)LL * 128 * 256];  // [n][k] fp16
__device__ float  g_psum[160 * HH];
__device__ float  g_psq[160 * HH];
__device__ float  g_mean[HH];
__device__ float  g_rstd[HH];

// ---------------- asm helpers -------------------------------------------------
__device__ __forceinline__ uint32_t smem_u32(const void* p) {
    uint32_t a;
    asm("{ .reg .u64 t; cvta.to.shared.u64 t, %1; cvt.u32.u64 %0, t; }"
        : "=r"(a) : "l"(p));
    return a;
}
#define CP_ASYNC16(dst, src) \
    asm volatile("cp.async.cg.shared.global [%0], [%1], 16;" :: "r"(dst), "l"(src))
#define CP_COMMIT() asm volatile("cp.async.commit_group;" ::: "memory")
#define CP_WAIT2()  asm volatile("cp.async.wait_group 2;" ::: "memory")
#define CP_WAIT1()  asm volatile("cp.async.wait_group 1;" ::: "memory")
#define CP_WAIT0()  asm volatile("cp.async.wait_group 0;" ::: "memory")

__device__ __forceinline__ void ldsm_x4(uint32_t& r0, uint32_t& r1,
                                        uint32_t& r2, uint32_t& r3, uint32_t addr) {
    asm volatile("ldmatrix.sync.aligned.m8n8.x4.shared.b16 {%0,%1,%2,%3}, [%4];"
        : "=r"(r0), "=r"(r1), "=r"(r2), "=r"(r3) : "r"(addr));
}

__device__ __forceinline__ void mma_f16(float* c, const uint32_t* a, const uint32_t* b) {
    asm volatile(
        "mma.sync.aligned.m16n8k16.row.col.f32.f16.f16.f32 "
        "{%0,%1,%2,%3}, {%4,%5,%6,%7}, {%8,%9}, {%0,%1,%2,%3};"
        : "+f"(c[0]), "+f"(c[1]), "+f"(c[2]), "+f"(c[3])
        : "r"(a[0]), "r"(a[1]), "r"(a[2]), "r"(a[3]), "r"(b[0]), "r"(b[1]));
}

// ---------------- single-block cooperative graph prep -----------------------
__global__ void prep_all(const int* __restrict__ ei, const float* __restrict__ ew) {
    int tid = threadIdx.x;                       // 1024 threads, 1 block
    for (int i = tid; i < NN; i += 1024) { g_deg[i] = 1.0f; g_cnt[i] = 1; }
    __syncthreads();
    for (int e = tid; e < EE; e += 1024) {
        int c = ei[EE + e];
        atomicAdd(&g_deg[c], ew[e]);
        atomicAdd(&g_cnt[c], 1);
    }
    __syncthreads();
    for (int i = tid; i < NN; i += 1024) g_dis[i] = rsqrtf(g_deg[i]);
    __syncthreads();
    __shared__ int sh[1024];
    __shared__ int carry;
    if (tid == 0) carry = 0;
    __syncthreads();
    for (int base = 0; base < NN; base += 1024) {
        int i = base + tid;
        int v = (i < NN) ? g_cnt[i] : 0;
        sh[tid] = v;
        __syncthreads();
        for (int off = 1; off < 1024; off <<= 1) {
            int t = (tid >= off) ? sh[tid - off] : 0;
            __syncthreads();
            sh[tid] += t;
            __syncthreads();
        }
        int excl = sh[tid] - v + carry;
        if (i < NN) g_ptr[i] = excl;
        __syncthreads();
        if (tid == 1023) carry += sh[1023];
        __syncthreads();
    }
    if (tid == 0) g_ptr[NN] = carry;
    __syncthreads();
    for (int i = tid; i < NN; i += 1024) {
        int p = g_ptr[i];
        g_src[p] = i;
        g_wv[p]  = g_dis[i] * g_dis[i];
        g_key[p] = -1;
        g_wpos[i] = p + 1;
    }
    __syncthreads();
    for (int e = tid; e < EE; e += 1024) {
        int r = ei[e];
        int c = ei[EE + e];
        int p = atomicAdd(&g_wpos[c], 1);
        g_src[p] = r;
        g_wv[p]  = g_dis[r] * ew[e] * g_dis[c];
        g_key[p] = e;
    }
    __syncthreads();
    for (int c = tid; c < NN; c += 1024) {
        int s0 = g_ptr[c] + 1, s1 = g_ptr[c + 1];
        for (int i = s0 + 1; i < s1; i++) {
            int k = g_key[i]; int sr = g_src[i]; float w = g_wv[i];
            int j = i - 1;
            while (j >= s0 && g_key[j] > k) {
                g_key[j + 1] = g_key[j]; g_src[j + 1] = g_src[j]; g_wv[j + 1] = g_wv[j];
                j--;
            }
            g_key[j + 1] = k; g_src[j + 1] = sr; g_wv[j + 1] = w;
        }
    }
    __syncthreads();
    // packed edge metadata: one 8B load per edge in the SpMM kernels
    for (int i = tid; i < NE; i += 1024) {
        uint2 m;
        m.x = (uint32_t)g_src[i] * 32u;
        m.y = __float_as_uint(g_wv[i]);
        g_ew[i] = m;
    }
}

// ---------------- weight pack (fp16) + zero h (fp32 + fp16) ------------------
#define W1 (LL * 256 * 256)
#define W2 (LL * 128 * 256)
#define W3 (LL * TT * HH)
#define MISC_BLOCKS ((W1 + W2 + 2 * W3 + 127) / 128)

__global__ void init_misc(const float* __restrict__ convW) {
    size_t i = (size_t)blockIdx.x * 128 + threadIdx.x;
    if (i < W1) {
        int l = (int)(i >> 16), rem = (int)(i & 65535);
        int n = rem >> 8, k = rem & 255;
        int g = n >> 7, j = n & 127;
        g_WruT[i] = __float2half(convW[((size_t)(l * 3 + g) * 256 + k) * 128 + j]);
    } else if (i < (size_t)W1 + W2) {
        size_t q = i - W1;
        int l = (int)(q >> 15), rem = (int)(q & 32767);
        int n = rem >> 8, k = rem & 255;
        g_WcT[q] = __float2half(convW[((size_t)(l * 3 + 2) * 256 + k) * 128 + n]);
    } else if (i < (size_t)W1 + W2 + W3) {
        g_h[i - W1 - W2] = 0.0f;
    } else if (i < (size_t)W1 + W2 + 2 * W3) {
        g_hf[i - W1 - W2 - W3] = __float2half(0.0f);
    }
}

// ---------------- lin_in, tiled: 64 nodes / 256-thread block -----------------
__global__ void __launch_bounds__(256) linin_tiled(const float* __restrict__ x_seq,
                                                   const float* __restrict__ W,
                                                   const float* __restrict__ bias) {
    __shared__ float sW[FF * HH];
    __shared__ float sx[64 * FF];
    __shared__ float sb[HH];
    int tid = threadIdx.x;
    size_t base = (size_t)blockIdx.x * 64;
    int s = (int)(base / TT);
    int t_base = (int)(base - (size_t)s * TT);

    for (int i = tid; i < FF * HH; i += 256) sW[i] = W[i];
    if (tid < HH) sb[tid] = bias[tid];
    {
        int node = tid >> 2, fg = (tid & 3) * 4;
        int t = t_base + node;
        int b = t / NN, n = t - b * NN;
        float4 v = *reinterpret_cast<const float4*>(
            &x_seq[(((size_t)b * SS + s) * NN + n) * FF + fg]);
        *reinterpret_cast<float4*>(&sx[node * FF + fg]) = v;
    }
    __syncthreads();

    int j = tid & 127, nh = tid >> 7;
    __half* outp = g_Xt + (size_t)s * TT * HH + (size_t)t_base * HH;
#pragma unroll 4
    for (int nd = nh * 32; nd < nh * 32 + 32; nd++) {
        float acc = sb[j];
#pragma unroll
        for (int k = 0; k < FF; k++) acc = fmaf(sx[nd * FF + k], sW[k * HH + j], acc);
        outp[(size_t)nd * HH + j] = __float2half(fmaxf(acc, 0.0f));
    }
}

// ---------------- SpMM gathers (packed edges, fp16 src, fp32 accumulate) -----
__global__ void __launch_bounds__(128) spmm_xh(int l, int s) {
    int tid = threadIdx.x;
    int t = blockIdx.x * 2 + (tid >> 6);
    int sub = (tid >> 5) & 1;
    int lane = tid & 31;
    int c = t % NN;
    int base = t - c;
    const __half* xsrc = (l == 0) ? (g_Xt + (size_t)s * TT * HH) : g_hf;
    const __half* S = sub ? (g_hf + (size_t)l * TT * HH) : xsrc;
    const uint2* p = reinterpret_cast<const uint2*>(S) + base * 32 + lane;
    int s0 = g_ptr[c], s1 = g_ptr[c + 1];
    float a0 = 0.f, a1 = 0.f, a2 = 0.f, a3 = 0.f;
    int e = s0;
    for (; e + 4 <= s1; e += 4) {
        uint2 m0 = g_ew[e],     m1 = g_ew[e + 1];
        uint2 m2 = g_ew[e + 2], m3 = g_ew[e + 3];
        float w0 = __uint_as_float(m0.y), w1 = __uint_as_float(m1.y);
        float w2 = __uint_as_float(m2.y), w3 = __uint_as_float(m3.y);
        uint2 v0 = __ldg(p + m0.x), v1 = __ldg(p + m1.x);
        uint2 v2 = __ldg(p + m2.x), v3 = __ldg(p + m3.x);
        float2 p00 = __half22float2(*reinterpret_cast<__half2*>(&v0.x));
        float2 p01 = __half22float2(*reinterpret_cast<__half2*>(&v0.y));
        float2 p10 = __half22float2(*reinterpret_cast<__half2*>(&v1.x));
        float2 p11 = __half22float2(*reinterpret_cast<__half2*>(&v1.y));
        float2 p20 = __half22float2(*reinterpret_cast<__half2*>(&v2.x));
        float2 p21 = __half22float2(*reinterpret_cast<__half2*>(&v2.y));
        float2 p30 = __half22float2(*reinterpret_cast<__half2*>(&v3.x));
        float2 p31 = __half22float2(*reinterpret_cast<__half2*>(&v3.y));
        a0 = fmaf(w0, p00.x, a0); a1 = fmaf(w0, p00.y, a1);
        a2 = fmaf(w0, p01.x, a2); a3 = fmaf(w0, p01.y, a3);
        a0 = fmaf(w1, p10.x, a0); a1 = fmaf(w1, p10.y, a1);
        a2 = fmaf(w1, p11.x, a2); a3 = fmaf(w1, p11.y, a3);
        a0 = fmaf(w2, p20.x, a0); a1 = fmaf(w2, p20.y, a1);
        a2 = fmaf(w2, p21.x, a2); a3 = fmaf(w2, p21.y, a3);
        a0 = fmaf(w3, p30.x, a0); a1 = fmaf(w3, p30.y, a1);
        a2 = fmaf(w3, p31.x, a2); a3 = fmaf(w3, p31.y, a3);
    }
    for (; e < s1; e++) {
        uint2 m = g_ew[e];
        float w = __uint_as_float(m.y);
        uint2 v = __ldg(p + m.x);
        float2 q0 = __half22float2(*reinterpret_cast<__half2*>(&v.x));
        float2 q1 = __half22float2(*reinterpret_cast<__half2*>(&v.y));
        a0 = fmaf(w, q0.x, a0); a1 = fmaf(w, q0.y, a1);
        a2 = fmaf(w, q1.x, a2); a3 = fmaf(w, q1.y, a3);
    }
    uint2 o;
    __half2 h0 = __floats2half2_rn(a0, a1);
    __half2 h1 = __floats2half2_rn(a2, a3);
    o.x = *reinterpret_cast<uint32_t*>(&h0);
    o.y = *reinterpret_cast<uint32_t*>(&h1);
    *(reinterpret_cast<uint2*>(g_AXH + t * 256 + sub * 128) + lane) = o;
}

__global__ void __launch_bounds__(128) spmm_rh() {
    int tid = threadIdx.x;
    int t = blockIdx.x * 4 + (tid >> 5);
    int lane = tid & 31;
    int c = t % NN;
    int base = t - c;
    const uint2* p = reinterpret_cast<const uint2*>(g_RH) + base * 32 + lane;
    int s0 = g_ptr[c], s1 = g_ptr[c + 1];
    float a0 = 0.f, a1 = 0.f, a2 = 0.f, a3 = 0.f;
    int e = s0;
    for (; e + 4 <= s1; e += 4) {
        uint2 m0 = g_ew[e],     m1 = g_ew[e + 1];
        uint2 m2 = g_ew[e + 2], m3 = g_ew[e + 3];
        float w0 = __uint_as_float(m0.y), w1 = __uint_as_float(m1.y);
        float w2 = __uint_as_float(m2.y), w3 = __uint_as_float(m3.y);
        uint2 v0 = __ldg(p + m0.x), v1 = __ldg(p + m1.x);
        uint2 v2 = __ldg(p + m2.x), v3 = __ldg(p + m3.x);
        float2 p00 = __half22float2(*reinterpret_cast<__half2*>(&v0.x));
        float2 p01 = __half22float2(*reinterpret_cast<__half2*>(&v0.y));
        float2 p10 = __half22float2(*reinterpret_cast<__half2*>(&v1.x));
        float2 p11 = __half22float2(*reinterpret_cast<__half2*>(&v1.y));
        float2 p20 = __half22float2(*reinterpret_cast<__half2*>(&v2.x));
        float2 p21 = __half22float2(*reinterpret_cast<__half2*>(&v2.y));
        float2 p30 = __half22float2(*reinterpret_cast<__half2*>(&v3.x));
        float2 p31 = __half22float2(*reinterpret_cast<__half2*>(&v3.y));
        a0 = fmaf(w0, p00.x, a0); a1 = fmaf(w0, p00.y, a1);
        a2 = fmaf(w0, p01.x, a2); a3 = fmaf(w0, p01.y, a3);
        a0 = fmaf(w1, p10.x, a0); a1 = fmaf(w1, p10.y, a1);
        a2 = fmaf(w1, p11.x, a2); a3 = fmaf(w1, p11.y, a3);
        a0 = fmaf(w2, p20.x, a0); a1 = fmaf(w2, p20.y, a1);
        a2 = fmaf(w2, p21.x, a2); a3 = fmaf(w2, p21.y, a3);
        a0 = fmaf(w3, p30.x, a0); a1 = fmaf(w3, p30.y, a1);
        a2 = fmaf(w3, p31.x, a2); a3 = fmaf(w3, p31.y, a3);
    }
    for (; e < s1; e++) {
        uint2 m = g_ew[e];
        float w = __uint_as_float(m.y);
        uint2 v = __ldg(p + m.x);
        float2 q0 = __half22float2(*reinterpret_cast<__half2*>(&v.x));
        float2 q1 = __half22float2(*reinterpret_cast<__half2*>(&v.y));
        a0 = fmaf(w, q0.x, a0); a1 = fmaf(w, q0.y, a1);
        a2 = fmaf(w, q1.x, a2); a3 = fmaf(w, q1.y, a3);
    }
    uint2 o;
    __half2 h0 = __floats2half2_rn(a0, a1);
    __half2 h1 = __floats2half2_rn(a2, a3);
    o.x = *reinterpret_cast<uint32_t*>(&h0);
    o.y = *reinterpret_cast<uint32_t*>(&h1);
    *(reinterpret_cast<uint2*>(g_AXH + t * 256 + 128) + lane) = o;
}

// ---------------- fp16 mma.sync GEMMs, M=64 tiles, 3 CTAs/SM -----------------
#define LDM2 20                          // u32 per row per chunk (16 data + 4 pad)
#define A64STG_U32 (64 * LDM2)           // A stage: 1280 u32 = 5120 B
#define A64STG_B   (A64STG_U32 * 4)
#define B64STG_U32 (128 * LDM2)          // B stage: 2560 u32 = 10240 B
#define B64STG_B   (B64STG_U32 * 4)
#define GSMEM64 (4 * (A64STG_U32 + B64STG_U32) * 4)   // 61440 B

// -------- r|u GEMM: 256 threads, tile 64x128, blockIdx.y = gate --------------
__global__ void __launch_bounds__(256, 3) gemm_ru(int l, const float* __restrict__ convB) {
    extern __shared__ uint32_t smem[];
    uint32_t* As = smem;                   // [4][A64STG_U32]
    uint32_t* Bs = smem + 4 * A64STG_U32;  // [4][B64STG_U32]

    int tid = threadIdx.x;
    int wid = tid >> 5, lane = tid & 31;
    int row_in = lane >> 2, kq = lane & 3;
    int wm = wid & 1, wn = wid >> 1;       // 2x4 warp grid, warp tile 32x32
    int m0 = blockIdx.x * 64;
    int y  = blockIdx.y;                   // 0 = r gate, 1 = u gate

    const __half* WT  = g_WruT + (size_t)l * 256 * 256 + (size_t)y * 128 * 256;
    const float* bias = convB + (size_t)l * 3 * HH + (size_t)y * HH;

    const __half* asrc;
    uint32_t adst;
    {
        int row = tid >> 2, q = tid & 3;
        asrc = g_AXH + (size_t)(m0 + row) * 256 + q * 8;
        adst = smem_u32(As) + (uint32_t)(row * LDM2 + q * 4) * 4u;
    }
    const __half* bsrc[2];
    uint32_t bdst[2];
#pragma unroll
    for (int it = 0; it < 2; it++) {
        int idx = tid + it * 256;
        int row = idx >> 2, q = idx & 3;
        bsrc[it] = WT + (size_t)row * 256 + q * 8;
        bdst[it] = smem_u32(Bs) + (uint32_t)(row * LDM2 + q * 4) * 4u;
    }

    uint32_t aoff[2], boff[2];
#pragma unroll
    for (int i = 0; i < 2; i++)
        aoff[i] = (uint32_t)((wm * 32 + i * 16 + (lane & 15)) * LDM2 + (lane >> 4) * 4) * 4u;
#pragma unroll
    for (int jp = 0; jp < 2; jp++)
        boff[jp] = (uint32_t)((wn * 32 + jp * 16 + (lane & 15)) * LDM2 + (lane >> 4) * 4) * 4u;
    uint32_t abase0 = smem_u32(As), bbase0 = smem_u32(Bs);

    float acc[2][4][4];
#pragma unroll
    for (int i = 0; i < 2; i++)
#pragma unroll
        for (int j = 0; j < 4; j++)
#pragma unroll
            for (int q = 0; q < 4; q++) acc[i][j][q] = 0.0f;

#pragma unroll
    for (int pc = 0; pc < 3; pc++) {
        CP_ASYNC16(adst + pc * A64STG_B, asrc + pc * 32);
#pragma unroll
        for (int it = 0; it < 2; it++)
            CP_ASYNC16(bdst[it] + pc * B64STG_B, bsrc[it] + pc * 32);
        CP_COMMIT();
    }

#pragma unroll
    for (int kc = 0; kc < 8; kc++) {
        if (kc < 6) CP_WAIT2();
        else if (kc == 6) CP_WAIT1();
        else CP_WAIT0();
        __syncthreads();
        if (kc + 3 < 8) {
            int nst = (kc + 3) & 3;
            CP_ASYNC16(adst + nst * A64STG_B, asrc + (kc + 3) * 32);
#pragma unroll
            for (int it = 0; it < 2; it++)
                CP_ASYNC16(bdst[it] + nst * B64STG_B, bsrc[it] + (kc + 3) * 32);
            CP_COMMIT();
        }
        uint32_t abase = abase0 + (kc & 3) * A64STG_B;
        uint32_t bbase = bbase0 + (kc & 3) * B64STG_B;
#pragma unroll
        for (int ks = 0; ks < 2; ks++) {
            uint32_t a[2][4], b[4][2];
#pragma unroll
            for (int i = 0; i < 2; i++)
                ldsm_x4(a[i][0], a[i][1], a[i][2], a[i][3], abase + aoff[i] + ks * 32);
#pragma unroll
            for (int jp = 0; jp < 2; jp++)
                ldsm_x4(b[2 * jp][0], b[2 * jp + 1][0], b[2 * jp][1], b[2 * jp + 1][1],
                        bbase + boff[jp] + ks * 32);
#pragma unroll
            for (int i = 0; i < 2; i++)
#pragma unroll
                for (int j = 0; j < 4; j++)
                    mma_f16(acc[i][j], a[i], b[j]);
        }
    }

    const float* Hst = g_h + (size_t)l * TT * HH;
#pragma unroll
    for (int i = 0; i < 2; i++) {
        int r0 = m0 + wm * 32 + i * 16 + row_in;
#pragma unroll
        for (int half = 0; half < 2; half++) {
            int m = r0 + half * 8;
#pragma unroll
            for (int j = 0; j < 4; j++) {
                int n = wn * 32 + j * 8 + 2 * kq;     // 0..127 within gate
                float v0 = acc[i][j][half * 2 + 0] + bias[n];
                float v1 = acc[i][j][half * 2 + 1] + bias[n + 1];
                float s0 = 1.0f / (1.0f + expf(-v0));
                float s1 = 1.0f / (1.0f + expf(-v1));
                size_t o = (size_t)m * HH + n;
                if (y == 0) {
                    float2 hv = *reinterpret_cast<const float2*>(&Hst[o]);
                    __half2 rv = __floats2half2_rn(s0 * hv.x, s1 * hv.y);
                    *reinterpret_cast<__half2*>(&g_RH[o]) = rv;
                } else {
                    *reinterpret_cast<__half2*>(&g_U[o]) = __floats2half2_rn(s0, s1);
                }
            }
        }
    }
}

// -------- candidate GEMM: 256 threads, tile 64x128 ---------------------------
__global__ void __launch_bounds__(256, 3) gemm_c(int l, const float* __restrict__ convB) {
    extern __shared__ uint32_t smem[];
    uint32_t* As = smem;                   // [4][A64STG_U32]
    uint32_t* Bs = smem + 4 * A64STG_U32;  // [4][B64STG_U32]

    int tid = threadIdx.x;
    int wid = tid >> 5, lane = tid & 31;
    int row_in = lane >> 2, kq = lane & 3;
    int wm = wid & 1, wn = wid >> 1;       // 2x4 warp grid
    int m0 = blockIdx.x * 64;

    const __half* WT  = g_WcT + (size_t)l * 128 * 256;
    const float* bias = convB + (size_t)(l * 3 + 2) * HH;

    const __half* asrc;
    uint32_t adst;
    {
        int row = tid >> 2, q = tid & 3;
        asrc = g_AXH + (size_t)(m0 + row) * 256 + q * 8;
        adst = smem_u32(As) + (uint32_t)(row * LDM2 + q * 4) * 4u;
    }
    const __half* bsrc[2];
    uint32_t bdst[2];
#pragma unroll
    for (int it = 0; it < 2; it++) {
        int idx = tid + it * 256;
        int row = idx >> 2, q = idx & 3;
        bsrc[it] = WT + (size_t)row * 256 + q * 8;
        bdst[it] = smem_u32(Bs) + (uint32_t)(row * LDM2 + q * 4) * 4u;
    }

    uint32_t aoff[2], boff[2];
#pragma unroll
    for (int i = 0; i < 2; i++)
        aoff[i] = (uint32_t)((wm * 32 + i * 16 + (lane & 15)) * LDM2 + (lane >> 4) * 4) * 4u;
#pragma unroll
    for (int jp = 0; jp < 2; jp++)
        boff[jp] = (uint32_t)((wn * 32 + jp * 16 + (lane & 15)) * LDM2 + (lane >> 4) * 4) * 4u;
    uint32_t abase0 = smem_u32(As), bbase0 = smem_u32(Bs);

    float acc[2][4][4];
#pragma unroll
    for (int i = 0; i < 2; i++)
#pragma unroll
        for (int j = 0; j < 4; j++)
#pragma unroll
            for (int q = 0; q < 4; q++) acc[i][j][q] = 0.0f;

#pragma unroll
    for (int pc = 0; pc < 3; pc++) {
        CP_ASYNC16(adst + pc * A64STG_B, asrc + pc * 32);
#pragma unroll
        for (int it = 0; it < 2; it++)
            CP_ASYNC16(bdst[it] + pc * B64STG_B, bsrc[it] + pc * 32);
        CP_COMMIT();
    }

#pragma unroll
    for (int kc = 0; kc < 8; kc++) {
        if (kc < 6) CP_WAIT2();
        else if (kc == 6) CP_WAIT1();
        else CP_WAIT0();
        __syncthreads();
        if (kc + 3 < 8) {
            int nst = (kc + 3) & 3;
            CP_ASYNC16(adst + nst * A64STG_B, asrc + (kc + 3) * 32);
#pragma unroll
            for (int it = 0; it < 2; it++)
                CP_ASYNC16(bdst[it] + nst * B64STG_B, bsrc[it] + (kc + 3) * 32);
            CP_COMMIT();
        }
        uint32_t abase = abase0 + (kc & 3) * A64STG_B;
        uint32_t bbase = bbase0 + (kc & 3) * B64STG_B;
#pragma unroll
        for (int ks = 0; ks < 2; ks++) {
            uint32_t a[2][4], b[4][2];
#pragma unroll
            for (int i = 0; i < 2; i++)
                ldsm_x4(a[i][0], a[i][1], a[i][2], a[i][3], abase + aoff[i] + ks * 32);
#pragma unroll
            for (int jp = 0; jp < 2; jp++)
                ldsm_x4(b[2 * jp][0], b[2 * jp + 1][0], b[2 * jp][1], b[2 * jp + 1][1],
                        bbase + boff[jp] + ks * 32);
#pragma unroll
            for (int i = 0; i < 2; i++)
#pragma unroll
                for (int j = 0; j < 4; j++)
                    mma_f16(acc[i][j], a[i], b[j]);
        }
    }

    float* Hst = g_h + (size_t)l * TT * HH;
    __half* Hf = g_hf + (size_t)l * TT * HH;
#pragma unroll
    for (int i = 0; i < 2; i++) {
        int r0 = m0 + wm * 32 + i * 16 + row_in;
#pragma unroll
        for (int half = 0; half < 2; half++) {
            int m = r0 + half * 8;
#pragma unroll
            for (int j = 0; j < 4; j++) {
                int n = wn * 32 + j * 8 + 2 * kq;
                float v0 = acc[i][j][half * 2 + 0] + bias[n];
                float v1 = acc[i][j][half * 2 + 1] + bias[n + 1];
                float c0 = tanhf(v0), c1 = tanhf(v1);
                size_t o = (size_t)m * HH + n;
                float2 uv = __half22float2(*reinterpret_cast<const __half2*>(&g_U[o]));
                float2 hv = *reinterpret_cast<const float2*>(&Hst[o]);
                hv.x = uv.x * hv.x + (1.0f - uv.x) * c0;
                hv.y = uv.y * hv.y + (1.0f - uv.y) * c1;
                *reinterpret_cast<float2*>(&Hst[o]) = hv;
                *reinterpret_cast<__half2*>(&Hf[o]) = __floats2half2_rn(hv.x, hv.y);
            }
        }
    }
}

// ---------------- batchnorm + output -----------------------------------------
__global__ void bn_partial() {
    int j = threadIdx.x;
    int b = blockIdx.x;
    const float* h1 = g_h + (size_t)(LL - 1) * TT * HH;
    float s = 0.0f, q = 0.0f;
    int r0 = b * (TT / 160), r1 = r0 + (TT / 160);
    for (int r = r0; r < r1; r++) {
        float v = h1[(size_t)r * HH + j];
        s += v; q += v * v;
    }
    g_psum[b * HH + j] = s;
    g_psq[b * HH + j]  = q;
}

__global__ void bn_final() {
    int j = threadIdx.x;
    float s = 0.0f, q = 0.0f;
    for (int b = 0; b < 160; b++) { s += g_psum[b * HH + j]; q += g_psq[b * HH + j]; }
    float m = s / (float)TT;
    float var = q / (float)TT - m * m;
    g_mean[j] = m;
    g_rstd[j] = rsqrtf(var + 1e-5f);
}

__global__ void final_kernel(const float* __restrict__ Wout,
                             const float* __restrict__ bout,
                             const float* __restrict__ gamma,
                             const float* __restrict__ beta,
                             float* __restrict__ out) {
    int warp = (blockIdx.x * blockDim.x + threadIdx.x) >> 5;
    int lane = threadIdx.x & 31;
    if (warp >= TT) return;
    const float* h1 = g_h + (size_t)(LL - 1) * TT * HH + (size_t)warp * HH;
    float a0 = 0.f, a1 = 0.f, a2 = 0.f, a3 = 0.f;
    for (int k = lane; k < HH; k += 32) {
        float v = (h1[k] - g_mean[k]) * g_rstd[k] * gamma[k] + beta[k];
        v = fmaxf(v, 0.0f);
        a0 = fmaf(v, Wout[k * 4 + 0], a0);
        a1 = fmaf(v, Wout[k * 4 + 1], a1);
        a2 = fmaf(v, Wout[k * 4 + 2], a2);
        a3 = fmaf(v, Wout[k * 4 + 3], a3);
    }
#pragma unroll
    for (int o = 16; o; o >>= 1) {
        a0 += __shfl_xor_sync(0xFFFFFFFFu, a0, o);
        a1 += __shfl_xor_sync(0xFFFFFFFFu, a1, o);
        a2 += __shfl_xor_sync(0xFFFFFFFFu, a2, o);
        a3 += __shfl_xor_sync(0xFFFFFFFFu, a3, o);
    }
    if (lane == 0) {
        a0 += bout[0]; a1 += bout[1]; a2 += bout[2]; a3 += bout[3];
        float mx = fmaxf(fmaxf(a0, a1), fmaxf(a2, a3));
        float se = expf(a0 - mx) + expf(a1 - mx) + expf(a2 - mx) + expf(a3 - mx);
        float lse = mx + logf(se);
        out[(size_t)warp * 4 + 0] = a0 - lse;
        out[(size_t)warp * 4 + 1] = a1 - lse;
        out[(size_t)warp * 4 + 2] = a2 - lse;
        out[(size_t)warp * 4 + 3] = a3 - lse;
    }
}

// ---------------- host orchestration -----------------------------------------
extern "C" void kernel_launch(void* const* d_in, const int* in_sizes, int n_in,
                              void* d_out, int out_size) {
    const float* x_seq      = (const float*)d_in[0];
    const int*   edge_index = (const int*)  d_in[1];
    const float* edge_weight= (const float*)d_in[2];
    const float* lin_in_W   = (const float*)d_in[3];
    const float* lin_in_b   = (const float*)d_in[4];
    const float* convW      = (const float*)d_in[5];
    const float* convB      = (const float*)d_in[6];
    const float* bn_gamma   = (const float*)d_in[7];
    const float* bn_beta    = (const float*)d_in[8];
    const float* lin_out_W  = (const float*)d_in[9];
    const float* lin_out_b  = (const float*)d_in[10];
    float* out = (float*)d_out;
    (void)in_sizes; (void)n_in; (void)out_size;

    cudaFuncSetAttribute(gemm_ru, cudaFuncAttributeMaxDynamicSharedMemorySize, GSMEM64);
    cudaFuncSetAttribute(gemm_c,  cudaFuncAttributeMaxDynamicSharedMemorySize, GSMEM64);

    // launches: 1 prep, 2 init_misc, 3 linin_tiled, 4 spmm_xh (ncu slot)
    prep_all<<<1, 1024>>>(edge_index, edge_weight);
    init_misc<<<MISC_BLOCKS, 128>>>(convW);
    linin_tiled<<<SS * TT / 64, 256>>>(x_seq, lin_in_W, lin_in_b);

    dim3 gridRU(TT / 64, 2);     // 625 x 2
    int  gridC = TT / 64;        // 625

    for (int s = 0; s < SS; s++) {
        for (int l = 0; l < LL; l++) {
            spmm_xh<<<TT / 2, 128>>>(l, s);
            gemm_ru<<<gridRU, 256, GSMEM64>>>(l, convB);
            spmm_rh<<<TT / 4, 128>>>();
            gemm_c<<<gridC, 256, GSMEM64>>>(l, convB);
        }
    }

    bn_partial<<<160, 128>>>();
    bn_final<<<1, 128>>>();
    final_kernel<<<(TT * 32 + 255) / 256, 256>>>(lin_out_W, lin_out_b,
                                                 bn_gamma, bn_beta, out);
}

// round 16
// speedup vs baseline: 1.4943x; 1.1130x over previous
#include <cuda_runtime.h>
#include <cuda_fp16.h>
#include <math.h>
#include <cstdint>

#define NN 5000
#define BB 8
#define TT 40000      // BB*NN
#define EE 40000
#define SS 12
#define FF 16
#define HH 128
#define LL 2
#define NE (EE + NN)  // CSR entries (edges + self loops)

// ---------------- device scratch (static: no allocation allowed) ------------
__device__ float g_deg[NN];
__device__ float g_dis[NN];
__device__ int   g_cnt[NN];
__device__ int   g_ptr[NN + 1];
__device__ int   g_wpos[NN];
__device__ int   g_src[NE];
__device__ float g_wv[NE];
__device__ int   g_key[NE];
__device__ uint2 g_ew[NE];   // packed: .x = src*32 (uint2 elems), .y = w bits

__device__ __half g_Xt[(size_t)SS * TT * HH];       // relu(lin_in), all steps
__device__ float  g_h[(size_t)LL * TT * HH];        // hidden fp32 (master)
__device__ __half g_hf[(size_t)LL * TT * HH];       // fp16 copy (gather src)
__device__ __half g_AXH[(size_t)LL * TT * 2 * HH];  // per-layer [Ax|Ah]/[Ax|Arh]
__device__ __half g_RH[(size_t)LL * TT * HH];       // per-layer r*h fp16
__device__ __half g_U[(size_t)LL * TT * HH];        // per-layer u fp16
__device__ __half g_WruT[(size_t)LL * 256 * 256];
__device__ __half g_WcT[(size_t)LL * 128 * 256];
__device__ float  g_psum[160 * HH];
__device__ float  g_psq[160 * HH];
__device__ float  g_mean[HH];
__device__ float  g_rstd[HH];

// ---------------- asm helpers -------------------------------------------------
__device__ __forceinline__ uint32_t smem_u32(const void* p) {
    uint32_t a;
    asm("{ .reg .u64 t; cvta.to.shared.u64 t, %1; cvt.u32.u64 %0, t; }"
        : "=r"(a) : "l"(p));
    return a;
}
#define CP_ASYNC16(dst, src) \
    asm volatile("cp.async.cg.shared.global [%0], [%1], 16;" :: "r"(dst), "l"(src))
#define CP_COMMIT() asm volatile("cp.async.commit_group;" ::: "memory")
#define CP_WAIT2()  asm volatile("cp.async.wait_group 2;" ::: "memory")
#define CP_WAIT1()  asm volatile("cp.async.wait_group 1;" ::: "memory")
#define CP_WAIT0()  asm volatile("cp.async.wait_group 0;" ::: "memory")

__device__ __forceinline__ void ldsm_x4(uint32_t& r0, uint32_t& r1,
                                        uint32_t& r2, uint32_t& r3, uint32_t addr) {
    asm volatile("ldmatrix.sync.aligned.m8n8.x4.shared.b16 {%0,%1,%2,%3}, [%4];"
        : "=r"(r0), "=r"(r1), "=r"(r2), "=r"(r3) : "r"(addr));
}

__device__ __forceinline__ void mma_f16(float* c, const uint32_t* a, const uint32_t* b) {
    asm volatile(
        "mma.sync.aligned.m16n8k16.row.col.f32.f16.f16.f32 "
        "{%0,%1,%2,%3}, {%4,%5,%6,%7}, {%8,%9}, {%0,%1,%2,%3};"
        : "+f"(c[0]), "+f"(c[1]), "+f"(c[2]), "+f"(c[3])
        : "r"(a[0]), "r"(a[1]), "r"(a[2]), "r"(a[3]), "r"(b[0]), "r"(b[1]));
}

// ---------------- single-block cooperative graph prep -----------------------
__global__ void prep_all(const int* __restrict__ ei, const float* __restrict__ ew) {
    int tid = threadIdx.x;                       // 1024 threads, 1 block
    for (int i = tid; i < NN; i += 1024) { g_deg[i] = 1.0f; g_cnt[i] = 1; }
    __syncthreads();
    for (int e = tid; e < EE; e += 1024) {
        int c = ei[EE + e];
        atomicAdd(&g_deg[c], ew[e]);
        atomicAdd(&g_cnt[c], 1);
    }
    __syncthreads();
    for (int i = tid; i < NN; i += 1024) g_dis[i] = rsqrtf(g_deg[i]);
    __syncthreads();
    __shared__ int sh[1024];
    __shared__ int carry;
    if (tid == 0) carry = 0;
    __syncthreads();
    for (int base = 0; base < NN; base += 1024) {
        int i = base + tid;
        int v = (i < NN) ? g_cnt[i] : 0;
        sh[tid] = v;
        __syncthreads();
        for (int off = 1; off < 1024; off <<= 1) {
            int t = (tid >= off) ? sh[tid - off] : 0;
            __syncthreads();
            sh[tid] += t;
            __syncthreads();
        }
        int excl = sh[tid] - v + carry;
        if (i < NN) g_ptr[i] = excl;
        __syncthreads();
        if (tid == 1023) carry += sh[1023];
        __syncthreads();
    }
    if (tid == 0) g_ptr[NN] = carry;
    __syncthreads();
    for (int i = tid; i < NN; i += 1024) {
        int p = g_ptr[i];
        g_src[p] = i;
        g_wv[p]  = g_dis[i] * g_dis[i];
        g_key[p] = -1;
        g_wpos[i] = p + 1;
    }
    __syncthreads();
    for (int e = tid; e < EE; e += 1024) {
        int r = ei[e];
        int c = ei[EE + e];
        int p = atomicAdd(&g_wpos[c], 1);
        g_src[p] = r;
        g_wv[p]  = g_dis[r] * ew[e] * g_dis[c];
        g_key[p] = e;
    }
    __syncthreads();
    for (int c = tid; c < NN; c += 1024) {
        int s0 = g_ptr[c] + 1, s1 = g_ptr[c + 1];
        for (int i = s0 + 1; i < s1; i++) {
            int k = g_key[i]; int sr = g_src[i]; float w = g_wv[i];
            int j = i - 1;
            while (j >= s0 && g_key[j] > k) {
                g_key[j + 1] = g_key[j]; g_src[j + 1] = g_src[j]; g_wv[j + 1] = g_wv[j];
                j--;
            }
            g_key[j + 1] = k; g_src[j + 1] = sr; g_wv[j + 1] = w;
        }
    }
    __syncthreads();
    for (int i = tid; i < NE; i += 1024) {
        uint2 m;
        m.x = (uint32_t)g_src[i] * 32u;
        m.y = __float_as_uint(g_wv[i]);
        g_ew[i] = m;
    }
}

// ---------------- weight pack (fp16) + zero h (fp32 + fp16) ------------------
#define W1 (LL * 256 * 256)
#define W2 (LL * 128 * 256)
#define W3 (LL * TT * HH)
#define MISC_BLOCKS ((W1 + W2 + 2 * W3 + 127) / 128)

__global__ void init_misc(const float* __restrict__ convW) {
    size_t i = (size_t)blockIdx.x * 128 + threadIdx.x;
    if (i < W1) {
        int l = (int)(i >> 16), rem = (int)(i & 65535);
        int n = rem >> 8, k = rem & 255;
        int g = n >> 7, j = n & 127;
        g_WruT[i] = __float2half(convW[((size_t)(l * 3 + g) * 256 + k) * 128 + j]);
    } else if (i < (size_t)W1 + W2) {
        size_t q = i - W1;
        int l = (int)(q >> 15), rem = (int)(q & 32767);
        int n = rem >> 8, k = rem & 255;
        g_WcT[q] = __float2half(convW[((size_t)(l * 3 + 2) * 256 + k) * 128 + n]);
    } else if (i < (size_t)W1 + W2 + W3) {
        g_h[i - W1 - W2] = 0.0f;
    } else if (i < (size_t)W1 + W2 + 2 * W3) {
        g_hf[i - W1 - W2 - W3] = __float2half(0.0f);
    }
}

// ---------------- lin_in, tiled: 64 nodes / 256-thread block -----------------
__global__ void __launch_bounds__(256) linin_tiled(const float* __restrict__ x_seq,
                                                   const float* __restrict__ W,
                                                   const float* __restrict__ bias) {
    __shared__ float sW[FF * HH];
    __shared__ float sx[64 * FF];
    __shared__ float sb[HH];
    int tid = threadIdx.x;
    size_t base = (size_t)blockIdx.x * 64;
    int s = (int)(base / TT);
    int t_base = (int)(base - (size_t)s * TT);

    for (int i = tid; i < FF * HH; i += 256) sW[i] = W[i];
    if (tid < HH) sb[tid] = bias[tid];
    {
        int node = tid >> 2, fg = (tid & 3) * 4;
        int t = t_base + node;
        int b = t / NN, n = t - b * NN;
        float4 v = *reinterpret_cast<const float4*>(
            &x_seq[(((size_t)b * SS + s) * NN + n) * FF + fg]);
        *reinterpret_cast<float4*>(&sx[node * FF + fg]) = v;
    }
    __syncthreads();

    int j = tid & 127, nh = tid >> 7;
    __half* outp = g_Xt + (size_t)s * TT * HH + (size_t)t_base * HH;
#pragma unroll 4
    for (int nd = nh * 32; nd < nh * 32 + 32; nd++) {
        float acc = sb[j];
#pragma unroll
        for (int k = 0; k < FF; k++) acc = fmaf(sx[nd * FF + k], sW[k * HH + j], acc);
        outp[(size_t)nd * HH + j] = __float2half(fmaxf(acc, 0.0f));
    }
}

// ---------------- SpMM gathers (packed edges, fp16 src, fp32 accumulate) -----
__global__ void __launch_bounds__(128) spmm_xh(int l, int s) {
    int tid = threadIdx.x;
    int t = blockIdx.x * 2 + (tid >> 6);
    int sub = (tid >> 5) & 1;
    int lane = tid & 31;
    int c = t % NN;
    int base = t - c;
    const __half* xsrc = (l == 0) ? (g_Xt + (size_t)s * TT * HH) : g_hf;
    const __half* S = sub ? (g_hf + (size_t)l * TT * HH) : xsrc;
    const uint2* p = reinterpret_cast<const uint2*>(S) + base * 32 + lane;
    int s0 = g_ptr[c], s1 = g_ptr[c + 1];
    float a0 = 0.f, a1 = 0.f, a2 = 0.f, a3 = 0.f;
    int e = s0;
    for (; e + 4 <= s1; e += 4) {
        uint2 m0 = g_ew[e],     m1 = g_ew[e + 1];
        uint2 m2 = g_ew[e + 2], m3 = g_ew[e + 3];
        float w0 = __uint_as_float(m0.y), w1 = __uint_as_float(m1.y);
        float w2 = __uint_as_float(m2.y), w3 = __uint_as_float(m3.y);
        uint2 v0 = __ldg(p + m0.x), v1 = __ldg(p + m1.x);
        uint2 v2 = __ldg(p + m2.x), v3 = __ldg(p + m3.x);
        float2 p00 = __half22float2(*reinterpret_cast<__half2*>(&v0.x));
        float2 p01 = __half22float2(*reinterpret_cast<__half2*>(&v0.y));
        float2 p10 = __half22float2(*reinterpret_cast<__half2*>(&v1.x));
        float2 p11 = __half22float2(*reinterpret_cast<__half2*>(&v1.y));
        float2 p20 = __half22float2(*reinterpret_cast<__half2*>(&v2.x));
        float2 p21 = __half22float2(*reinterpret_cast<__half2*>(&v2.y));
        float2 p30 = __half22float2(*reinterpret_cast<__half2*>(&v3.x));
        float2 p31 = __half22float2(*reinterpret_cast<__half2*>(&v3.y));
        a0 = fmaf(w0, p00.x, a0); a1 = fmaf(w0, p00.y, a1);
        a2 = fmaf(w0, p01.x, a2); a3 = fmaf(w0, p01.y, a3);
        a0 = fmaf(w1, p10.x, a0); a1 = fmaf(w1, p10.y, a1);
        a2 = fmaf(w1, p11.x, a2); a3 = fmaf(w1, p11.y, a3);
        a0 = fmaf(w2, p20.x, a0); a1 = fmaf(w2, p20.y, a1);
        a2 = fmaf(w2, p21.x, a2); a3 = fmaf(w2, p21.y, a3);
        a0 = fmaf(w3, p30.x, a0); a1 = fmaf(w3, p30.y, a1);
        a2 = fmaf(w3, p31.x, a2); a3 = fmaf(w3, p31.y, a3);
    }
    for (; e < s1; e++) {
        uint2 m = g_ew[e];
        float w = __uint_as_float(m.y);
        uint2 v = __ldg(p + m.x);
        float2 q0 = __half22float2(*reinterpret_cast<__half2*>(&v.x));
        float2 q1 = __half22float2(*reinterpret_cast<__half2*>(&v.y));
        a0 = fmaf(w, q0.x, a0); a1 = fmaf(w, q0.y, a1);
        a2 = fmaf(w, q1.x, a2); a3 = fmaf(w, q1.y, a3);
    }
    uint2 o;
    __half2 h0 = __floats2half2_rn(a0, a1);
    __half2 h1 = __floats2half2_rn(a2, a3);
    o.x = *reinterpret_cast<uint32_t*>(&h0);
    o.y = *reinterpret_cast<uint32_t*>(&h1);
    *(reinterpret_cast<uint2*>(g_AXH + (size_t)l * TT * 256 + t * 256 + sub * 128) + lane) = o;
}

__global__ void __launch_bounds__(128) spmm_rh(int l) {
    int tid = threadIdx.x;
    int t = blockIdx.x * 4 + (tid >> 5);
    int lane = tid & 31;
    int c = t % NN;
    int base = t - c;
    const uint2* p = reinterpret_cast<const uint2*>(g_RH + (size_t)l * TT * HH) + base * 32 + lane;
    int s0 = g_ptr[c], s1 = g_ptr[c + 1];
    float a0 = 0.f, a1 = 0.f, a2 = 0.f, a3 = 0.f;
    int e = s0;
    for (; e + 4 <= s1; e += 4) {
        uint2 m0 = g_ew[e],     m1 = g_ew[e + 1];
        uint2 m2 = g_ew[e + 2], m3 = g_ew[e + 3];
        float w0 = __uint_as_float(m0.y), w1 = __uint_as_float(m1.y);
        float w2 = __uint_as_float(m2.y), w3 = __uint_as_float(m3.y);
        uint2 v0 = __ldg(p + m0.x), v1 = __ldg(p + m1.x);
        uint2 v2 = __ldg(p + m2.x), v3 = __ldg(p + m3.x);
        float2 p00 = __half22float2(*reinterpret_cast<__half2*>(&v0.x));
        float2 p01 = __half22float2(*reinterpret_cast<__half2*>(&v0.y));
        float2 p10 = __half22float2(*reinterpret_cast<__half2*>(&v1.x));
        float2 p11 = __half22float2(*reinterpret_cast<__half2*>(&v1.y));
        float2 p20 = __half22float2(*reinterpret_cast<__half2*>(&v2.x));
        float2 p21 = __half22float2(*reinterpret_cast<__half2*>(&v2.y));
        float2 p30 = __half22float2(*reinterpret_cast<__half2*>(&v3.x));
        float2 p31 = __half22float2(*reinterpret_cast<__half2*>(&v3.y));
        a0 = fmaf(w0, p00.x, a0); a1 = fmaf(w0, p00.y, a1);
        a2 = fmaf(w0, p01.x, a2); a3 = fmaf(w0, p01.y, a3);
        a0 = fmaf(w1, p10.x, a0); a1 = fmaf(w1, p10.y, a1);
        a2 = fmaf(w1, p11.x, a2); a3 = fmaf(w1, p11.y, a3);
        a0 = fmaf(w2, p20.x, a0); a1 = fmaf(w2, p20.y, a1);
        a2 = fmaf(w2, p21.x, a2); a3 = fmaf(w2, p21.y, a3);
        a0 = fmaf(w3, p30.x, a0); a1 = fmaf(w3, p30.y, a1);
        a2 = fmaf(w3, p31.x, a2); a3 = fmaf(w3, p31.y, a3);
    }
    for (; e < s1; e++) {
        uint2 m = g_ew[e];
        float w = __uint_as_float(m.y);
        uint2 v = __ldg(p + m.x);
        float2 q0 = __half22float2(*reinterpret_cast<__half2*>(&v.x));
        float2 q1 = __half22float2(*reinterpret_cast<__half2*>(&v.y));
        a0 = fmaf(w, q0.x, a0); a1 = fmaf(w, q0.y, a1);
        a2 = fmaf(w, q1.x, a2); a3 = fmaf(w, q1.y, a3);
    }
    uint2 o;
    __half2 h0 = __floats2half2_rn(a0, a1);
    __half2 h1 = __floats2half2_rn(a2, a3);
    o.x = *reinterpret_cast<uint32_t*>(&h0);
    o.y = *reinterpret_cast<uint32_t*>(&h1);
    *(reinterpret_cast<uint2*>(g_AXH + (size_t)l * TT * 256 + t * 256 + 128) + lane) = o;
}

// ---------------- fp16 mma.sync GEMMs, M=64 tiles, 3 CTAs/SM -----------------
#define LDM2 20                          // u32 per row per chunk (16 data + 4 pad)
#define A64STG_U32 (64 * LDM2)           // A stage: 1280 u32 = 5120 B
#define A64STG_B   (A64STG_U32 * 4)
#define B64STG_U32 (128 * LDM2)          // B stage: 2560 u32 = 10240 B
#define B64STG_B   (B64STG_U32 * 4)
#define GSMEM64 (4 * (A64STG_U32 + B64STG_U32) * 4)   // 61440 B

// -------- r|u GEMM: 256 threads, tile 64x128, blockIdx.y = gate --------------
__global__ void __launch_bounds__(256, 3) gemm_ru(int l, const float* __restrict__ convB) {
    extern __shared__ uint32_t smem[];
    uint32_t* As = smem;                   // [4][A64STG_U32]
    uint32_t* Bs = smem + 4 * A64STG_U32;  // [4][B64STG_U32]

    int tid = threadIdx.x;
    int wid = tid >> 5, lane = tid & 31;
    int row_in = lane >> 2, kq = lane & 3;
    int wm = wid & 1, wn = wid >> 1;       // 2x4 warp grid, warp tile 32x32
    int m0 = blockIdx.x * 64;
    int y  = blockIdx.y;                   // 0 = r gate, 1 = u gate

    const __half* WT  = g_WruT + (size_t)l * 256 * 256 + (size_t)y * 128 * 256;
    const float* bias = convB + (size_t)l * 3 * HH + (size_t)y * HH;
    const __half* AXH = g_AXH + (size_t)l * TT * 256;

    const __half* asrc;
    uint32_t adst;
    {
        int row = tid >> 2, q = tid & 3;
        asrc = AXH + (size_t)(m0 + row) * 256 + q * 8;
        adst = smem_u32(As) + (uint32_t)(row * LDM2 + q * 4) * 4u;
    }
    const __half* bsrc[2];
    uint32_t bdst[2];
#pragma unroll
    for (int it = 0; it < 2; it++) {
        int idx = tid + it * 256;
        int row = idx >> 2, q = idx & 3;
        bsrc[it] = WT + (size_t)row * 256 + q * 8;
        bdst[it] = smem_u32(Bs) + (uint32_t)(row * LDM2 + q * 4) * 4u;
    }

    uint32_t aoff[2], boff[2];
#pragma unroll
    for (int i = 0; i < 2; i++)
        aoff[i] = (uint32_t)((wm * 32 + i * 16 + (lane & 15)) * LDM2 + (lane >> 4) * 4) * 4u;
#pragma unroll
    for (int jp = 0; jp < 2; jp++)
        boff[jp] = (uint32_t)((wn * 32 + jp * 16 + (lane & 15)) * LDM2 + (lane >> 4) * 4) * 4u;
    uint32_t abase0 = smem_u32(As), bbase0 = smem_u32(Bs);

    float acc[2][4][4];
#pragma unroll
    for (int i = 0; i < 2; i++)
#pragma unroll
        for (int j = 0; j < 4; j++)
#pragma unroll
            for (int q = 0; q < 4; q++) acc[i][j][q] = 0.0f;

#pragma unroll
    for (int pc = 0; pc < 3; pc++) {
        CP_ASYNC16(adst + pc * A64STG_B, asrc + pc * 32);
#pragma unroll
        for (int it = 0; it < 2; it++)
            CP_ASYNC16(bdst[it] + pc * B64STG_B, bsrc[it] + pc * 32);
        CP_COMMIT();
    }

#pragma unroll
    for (int kc = 0; kc < 8; kc++) {
        if (kc < 6) CP_WAIT2();
        else if (kc == 6) CP_WAIT1();
        else CP_WAIT0();
        __syncthreads();
        if (kc + 3 < 8) {
            int nst = (kc + 3) & 3;
            CP_ASYNC16(adst + nst * A64STG_B, asrc + (kc + 3) * 32);
#pragma unroll
            for (int it = 0; it < 2; it++)
                CP_ASYNC16(bdst[it] + nst * B64STG_B, bsrc[it] + (kc + 3) * 32);
            CP_COMMIT();
        }
        uint32_t abase = abase0 + (kc & 3) * A64STG_B;
        uint32_t bbase = bbase0 + (kc & 3) * B64STG_B;
#pragma unroll
        for (int ks = 0; ks < 2; ks++) {
            uint32_t a[2][4], b[4][2];
#pragma unroll
            for (int i = 0; i < 2; i++)
                ldsm_x4(a[i][0], a[i][1], a[i][2], a[i][3], abase + aoff[i] + ks * 32);
#pragma unroll
            for (int jp = 0; jp < 2; jp++)
                ldsm_x4(b[2 * jp][0], b[2 * jp + 1][0], b[2 * jp][1], b[2 * jp + 1][1],
                        bbase + boff[jp] + ks * 32);
#pragma unroll
            for (int i = 0; i < 2; i++)
#pragma unroll
                for (int j = 0; j < 4; j++)
                    mma_f16(acc[i][j], a[i], b[j]);
        }
    }

    const float* Hst = g_h + (size_t)l * TT * HH;
    __half* RH = g_RH + (size_t)l * TT * HH;
    __half* U  = g_U  + (size_t)l * TT * HH;
#pragma unroll
    for (int i = 0; i < 2; i++) {
        int r0 = m0 + wm * 32 + i * 16 + row_in;
#pragma unroll
        for (int half = 0; half < 2; half++) {
            int m = r0 + half * 8;
#pragma unroll
            for (int j = 0; j < 4; j++) {
                int n = wn * 32 + j * 8 + 2 * kq;     // 0..127 within gate
                float v0 = acc[i][j][half * 2 + 0] + bias[n];
                float v1 = acc[i][j][half * 2 + 1] + bias[n + 1];
                float s0 = 1.0f / (1.0f + expf(-v0));
                float s1 = 1.0f / (1.0f + expf(-v1));
                size_t o = (size_t)m * HH + n;
                if (y == 0) {
                    float2 hv = *reinterpret_cast<const float2*>(&Hst[o]);
                    __half2 rv = __floats2half2_rn(s0 * hv.x, s1 * hv.y);
                    *reinterpret_cast<__half2*>(&RH[o]) = rv;
                } else {
                    *reinterpret_cast<__half2*>(&U[o]) = __floats2half2_rn(s0, s1);
                }
            }
        }
    }
}

// -------- candidate GEMM: 256 threads, tile 64x128 ---------------------------
__global__ void __launch_bounds__(256, 3) gemm_c(int l, const float* __restrict__ convB) {
    extern __shared__ uint32_t smem[];
    uint32_t* As = smem;                   // [4][A64STG_U32]
    uint32_t* Bs = smem + 4 * A64STG_U32;  // [4][B64STG_U32]

    int tid = threadIdx.x;
    int wid = tid >> 5, lane = tid & 31;
    int row_in = lane >> 2, kq = lane & 3;
    int wm = wid & 1, wn = wid >> 1;       // 2x4 warp grid
    int m0 = blockIdx.x * 64;

    const __half* WT  = g_WcT + (size_t)l * 128 * 256;
    const float* bias = convB + (size_t)(l * 3 + 2) * HH;
    const __half* AXH = g_AXH + (size_t)l * TT * 256;

    const __half* asrc;
    uint32_t adst;
    {
        int row = tid >> 2, q = tid & 3;
        asrc = AXH + (size_t)(m0 + row) * 256 + q * 8;
        adst = smem_u32(As) + (uint32_t)(row * LDM2 + q * 4) * 4u;
    }
    const __half* bsrc[2];
    uint32_t bdst[2];
#pragma unroll
    for (int it = 0; it < 2; it++) {
        int idx = tid + it * 256;
        int row = idx >> 2, q = idx & 3;
        bsrc[it] = WT + (size_t)row * 256 + q * 8;
        bdst[it] = smem_u32(Bs) + (uint32_t)(row * LDM2 + q * 4) * 4u;
    }

    uint32_t aoff[2], boff[2];
#pragma unroll
    for (int i = 0; i < 2; i++)
        aoff[i] = (uint32_t)((wm * 32 + i * 16 + (lane & 15)) * LDM2 + (lane >> 4) * 4) * 4u;
#pragma unroll
    for (int jp = 0; jp < 2; jp++)
        boff[jp] = (uint32_t)((wn * 32 + jp * 16 + (lane & 15)) * LDM2 + (lane >> 4) * 4) * 4u;
    uint32_t abase0 = smem_u32(As), bbase0 = smem_u32(Bs);

    float acc[2][4][4];
#pragma unroll
    for (int i = 0; i < 2; i++)
#pragma unroll
        for (int j = 0; j < 4; j++)
#pragma unroll
            for (int q = 0; q < 4; q++) acc[i][j][q] = 0.0f;

#pragma unroll
    for (int pc = 0; pc < 3; pc++) {
        CP_ASYNC16(adst + pc * A64STG_B, asrc + pc * 32);
#pragma unroll
        for (int it = 0; it < 2; it++)
            CP_ASYNC16(bdst[it] + pc * B64STG_B, bsrc[it] + pc * 32);
        CP_COMMIT();
    }

#pragma unroll
    for (int kc = 0; kc < 8; kc++) {
        if (kc < 6) CP_WAIT2();
        else if (kc == 6) CP_WAIT1();
        else CP_WAIT0();
        __syncthreads();
        if (kc + 3 < 8) {
            int nst = (kc + 3) & 3;
            CP_ASYNC16(adst + nst * A64STG_B, asrc + (kc + 3) * 32);
#pragma unroll
            for (int it = 0; it < 2; it++)
                CP_ASYNC16(bdst[it] + nst * B64STG_B, bsrc[it] + (kc + 3) * 32);
            CP_COMMIT();
        }
        uint32_t abase = abase0 + (kc & 3) * A64STG_B;
        uint32_t bbase = bbase0 + (kc & 3) * B64STG_B;
#pragma unroll
        for (int ks = 0; ks < 2; ks++) {
            uint32_t a[2][4], b[4][2];
#pragma unroll
            for (int i = 0; i < 2; i++)
                ldsm_x4(a[i][0], a[i][1], a[i][2], a[i][3], abase + aoff[i] + ks * 32);
#pragma unroll
            for (int jp = 0; jp < 2; jp++)
                ldsm_x4(b[2 * jp][0], b[2 * jp + 1][0], b[2 * jp][1], b[2 * jp + 1][1],
                        bbase + boff[jp] + ks * 32);
#pragma unroll
            for (int i = 0; i < 2; i++)
#pragma unroll
                for (int j = 0; j < 4; j++)
                    mma_f16(acc[i][j], a[i], b[j]);
        }
    }

    float* Hst = g_h + (size_t)l * TT * HH;
    __half* Hf = g_hf + (size_t)l * TT * HH;
    const __half* U = g_U + (size_t)l * TT * HH;
#pragma unroll
    for (int i = 0; i < 2; i++) {
        int r0 = m0 + wm * 32 + i * 16 + row_in;
#pragma unroll
        for (int half = 0; half < 2; half++) {
            int m = r0 + half * 8;
#pragma unroll
            for (int j = 0; j < 4; j++) {
                int n = wn * 32 + j * 8 + 2 * kq;
                float v0 = acc[i][j][half * 2 + 0] + bias[n];
                float v1 = acc[i][j][half * 2 + 1] + bias[n + 1];
                float c0 = tanhf(v0), c1 = tanhf(v1);
                size_t o = (size_t)m * HH + n;
                float2 uv = __half22float2(*reinterpret_cast<const __half2*>(&U[o]));
                float2 hv = *reinterpret_cast<const float2*>(&Hst[o]);
                hv.x = uv.x * hv.x + (1.0f - uv.x) * c0;
                hv.y = uv.y * hv.y + (1.0f - uv.y) * c1;
                *reinterpret_cast<float2*>(&Hst[o]) = hv;
                *reinterpret_cast<__half2*>(&Hf[o]) = __floats2half2_rn(hv.x, hv.y);
            }
        }
    }
}

// ---------------- batchnorm + output -----------------------------------------
__global__ void bn_partial() {
    int j = threadIdx.x;
    int b = blockIdx.x;
    const float* h1 = g_h + (size_t)(LL - 1) * TT * HH;
    float s = 0.0f, q = 0.0f;
    int r0 = b * (TT / 160), r1 = r0 + (TT / 160);
    for (int r = r0; r < r1; r++) {
        float v = h1[(size_t)r * HH + j];
        s += v; q += v * v;
    }
    g_psum[b * HH + j] = s;
    g_psq[b * HH + j]  = q;
}

__global__ void bn_final() {
    int j = threadIdx.x;
    float s = 0.0f, q = 0.0f;
    for (int b = 0; b < 160; b++) { s += g_psum[b * HH + j]; q += g_psq[b * HH + j]; }
    float m = s / (float)TT;
    float var = q / (float)TT - m * m;
    g_mean[j] = m;
    g_rstd[j] = rsqrtf(var + 1e-5f);
}

__global__ void final_kernel(const float* __restrict__ Wout,
                             const float* __restrict__ bout,
                             const float* __restrict__ gamma,
                             const float* __restrict__ beta,
                             float* __restrict__ out) {
    int warp = (blockIdx.x * blockDim.x + threadIdx.x) >> 5;
    int lane = threadIdx.x & 31;
    if (warp >= TT) return;
    const float* h1 = g_h + (size_t)(LL - 1) * TT * HH + (size_t)warp * HH;
    float a0 = 0.f, a1 = 0.f, a2 = 0.f, a3 = 0.f;
    for (int k = lane; k < HH; k += 32) {
        float v = (h1[k] - g_mean[k]) * g_rstd[k] * gamma[k] + beta[k];
        v = fmaxf(v, 0.0f);
        a0 = fmaf(v, Wout[k * 4 + 0], a0);
        a1 = fmaf(v, Wout[k * 4 + 1], a1);
        a2 = fmaf(v, Wout[k * 4 + 2], a2);
        a3 = fmaf(v, Wout[k * 4 + 3], a3);
    }
#pragma unroll
    for (int o = 16; o; o >>= 1) {
        a0 += __shfl_xor_sync(0xFFFFFFFFu, a0, o);
        a1 += __shfl_xor_sync(0xFFFFFFFFu, a1, o);
        a2 += __shfl_xor_sync(0xFFFFFFFFu, a2, o);
        a3 += __shfl_xor_sync(0xFFFFFFFFu, a3, o);
    }
    if (lane == 0) {
        a0 += bout[0]; a1 += bout[1]; a2 += bout[2]; a3 += bout[3];
        float mx = fmaxf(fmaxf(a0, a1), fmaxf(a2, a3));
        float se = expf(a0 - mx) + expf(a1 - mx) + expf(a2 - mx) + expf(a3 - mx);
        float lse = mx + logf(se);
        out[(size_t)warp * 4 + 0] = a0 - lse;
        out[(size_t)warp * 4 + 1] = a1 - lse;
        out[(size_t)warp * 4 + 2] = a2 - lse;
        out[(size_t)warp * 4 + 3] = a3 - lse;
    }
}

// ---------------- host orchestration -----------------------------------------
extern "C" void kernel_launch(void* const* d_in, const int* in_sizes, int n_in,
                              void* d_out, int out_size) {
    const float* x_seq      = (const float*)d_in[0];
    const int*   edge_index = (const int*)  d_in[1];
    const float* edge_weight= (const float*)d_in[2];
    const float* lin_in_W   = (const float*)d_in[3];
    const float* lin_in_b   = (const float*)d_in[4];
    const float* convW      = (const float*)d_in[5];
    const float* convB      = (const float*)d_in[6];
    const float* bn_gamma   = (const float*)d_in[7];
    const float* bn_beta    = (const float*)d_in[8];
    const float* lin_out_W  = (const float*)d_in[9];
    const float* lin_out_b  = (const float*)d_in[10];
    float* out = (float*)d_out;
    (void)in_sizes; (void)n_in; (void)out_size;

    // side stream + events, created once on first (pre-capture) call
    static cudaStream_t st1 = [] {
        cudaStream_t s; cudaStreamCreateWithFlags(&s, cudaStreamNonBlocking); return s;
    }();
    static cudaEvent_t evA = [] {
        cudaEvent_t e; cudaEventCreateWithFlags(&e, cudaEventDisableTiming); return e;
    }();
    static cudaEvent_t evB = [] {
        cudaEvent_t e; cudaEventCreateWithFlags(&e, cudaEventDisableTiming); return e;
    }();

    cudaFuncSetAttribute(gemm_ru, cudaFuncAttributeMaxDynamicSharedMemorySize, GSMEM64);
    cudaFuncSetAttribute(gemm_c,  cudaFuncAttributeMaxDynamicSharedMemorySize, GSMEM64);

    prep_all<<<1, 1024>>>(edge_index, edge_weight);
    init_misc<<<MISC_BLOCKS, 128>>>(convW);
    linin_tiled<<<SS * TT / 64, 256>>>(x_seq, lin_in_W, lin_in_b);

    dim3 gridRU(TT / 64, 2);     // 625 x 2
    int  gridC = TT / 64;        // 625

    for (int s = 0; s < SS; s++) {
        // layer 0 chain on the capture (legacy) stream
        spmm_xh<<<TT / 2, 128>>>(0, s);
        gemm_ru<<<gridRU, 256, GSMEM64>>>(0, convB);
        spmm_rh<<<TT / 4, 128>>>(0);
        gemm_c<<<gridC, 256, GSMEM64>>>(0, convB);
        cudaEventRecord(evA, 0);
        // layer 1 chain on side stream, gated on layer-0 h update of step s
        cudaStreamWaitEvent(st1, evA, 0);
        spmm_xh<<<TT / 2, 128, 0, st1>>>(1, s);
        gemm_ru<<<gridRU, 256, GSMEM64, st1>>>(1, convB);
        spmm_rh<<<TT / 4, 128, 0, st1>>>(1);
        gemm_c<<<gridC, 256, GSMEM64, st1>>>(1, convB);
        cudaEventRecord(evB, st1);
    }
    // join: BN depends on final layer-1 h
    cudaStreamWaitEvent(0, evB, 0);

    bn_partial<<<160, 128>>>();
    bn_final<<<1, 128>>>();
    final_kernel<<<(TT * 32 + 255) / 256, 256>>>(lin_out_W, lin_out_b,
                                                 bn_gamma, bn_beta, out);
}